// round 14
// baseline (speedup 1.0000x reference)
#include <cuda_runtime.h>
#include <cuda_fp16.h>
#include <cstdint>

// phi = (lam ⊙ (rho @ Cs^T)) @ Cs, rank-256. B=1024, N=4096, R=256.
// R14: (a) GEMM1 split-K via red.global.add.f32 into 1MB fp32 accumulator
//      (partials round-trip eliminated, k_reduce -> tiny k_scale);
//      (b) GEMM2 as high-occupancy variant: 512 thr, warp tile 32x32,
//      2 CTAs/SM -> 32 warps/SM (A/B vs GEMM1's proven 256-thr config).

#define NB 1024
#define NG 4096
#define RR 256
#define SPLITS 16
#define TA_EL 8192      // halfs per 128x64 tile
#define TB_EL 8192

__device__ __align__(16) __half g_A1[NB * NG];     // rho tiled    [8][64]
__device__ __align__(16) __half g_B1[RR * NG];     // Cs tiled     [2][64]
__device__ __align__(16) __half g_B2[NG * RR];     // Cs^T tiled   [32][4]
__device__ __align__(16) __half g_A2[NB * RR];     // Al tiled     [8][4]
__device__ __align__(16) float g_Acc[NB * RR];     // 1 MB split-K accumulator
__device__ __align__(16) float g_lut_c[16384];
__device__ __align__(16) float g_lut_s[16384];

// ----------------------------- PTX helpers ---------------------------------
__device__ __forceinline__ uint32_t smem_u32(const void* p) {
    uint32_t a;
    asm("{ .reg .u64 t; cvta.to.shared.u64 t, %1; cvt.u32.u64 %0, t; }" : "=r"(a) : "l"(p));
    return a;
}
#define MBARRIER_INIT(addr, cnt) \
    asm volatile("mbarrier.init.shared.b64 [%0], %1;" :: "r"((uint32_t)(addr)), "r"((uint32_t)(cnt)) : "memory")
#define MBARRIER_EXPECT_TX(addr, bytes) \
    asm volatile("mbarrier.arrive.expect_tx.shared.b64 _, [%0], %1;" \
        :: "r"((uint32_t)(addr)), "r"((uint32_t)(bytes)) : "memory")
#define MBARRIER_WAIT_PARITY(addr, par) do { \
    uint32_t _mb = (uint32_t)(addr), _pa = (uint32_t)(par), _dn; \
    asm volatile("{\n\t.reg .pred p;\n\t" \
        "mbarrier.try_wait.parity.acquire.cta.shared::cta.b64 p, [%1], %2;\n\t" \
        "selp.b32 %0, 1, 0, p;\n\t}" : "=r"(_dn) : "r"(_mb), "r"(_pa) : "memory"); \
    if (!_dn) { \
        asm volatile("{\n\t.reg .pred P1;\n\tWL_%=:\n\t" \
            "mbarrier.try_wait.parity.acquire.cta.shared::cta.b64 P1, [%0], %1, 0x989680;\n\t" \
            "@P1 bra.uni WD_%=;\n\tbra.uni WL_%=;\n\tWD_%=:\n\t}" \
            :: "r"(_mb), "r"(_pa) : "memory"); \
    } } while (0)
#define BULK_G2S(dst, src, bytes, mbar) \
    asm volatile("cp.async.bulk.shared::cluster.global.mbarrier::complete_tx::bytes " \
                 "[%0], [%1], %2, [%3];" \
        :: "r"((uint32_t)(dst)), "l"(src), "r"((uint32_t)(bytes)), "r"((uint32_t)(mbar)) : "memory")
#define LDSM4(r, a) \
    asm volatile("ldmatrix.sync.aligned.m8n8.x4.shared.b16 {%0,%1,%2,%3}, [%4];" \
        : "=r"((r)[0]), "=r"((r)[1]), "=r"((r)[2]), "=r"((r)[3]) : "r"(a))
#define MMA(c, a, b0, b1) \
    asm volatile("mma.sync.aligned.m16n8k16.row.col.f32.f16.f16.f32 " \
        "{%0,%1,%2,%3},{%4,%5,%6,%7},{%8,%9},{%0,%1,%2,%3};" \
        : "+f"((c)[0]), "+f"((c)[1]), "+f"((c)[2]), "+f"((c)[3]) \
        : "r"((a)[0]), "r"((a)[1]), "r"((a)[2]), "r"((a)[3]), "r"(b0), "r"(b1))
#define REDADD(addr, v) \
    asm volatile("red.global.add.f32 [%0], %1;" :: "l"(addr), "f"(v) : "memory")

// Tile-internal offset (halfs): 64 halfs/row = 128 B; 16B unit u swizzled by row&7.
__device__ __forceinline__ int tile_off(int r, int kcol) {
    int u = kcol >> 3;
    return r * 64 + ((u ^ (r & 7)) << 3) + (kcol & 7);
}

// ------------------------------- LUT + builds -------------------------------
__global__ void k_lut() {            // also zeroes g_Acc (replayed per launch)
    int j = blockIdx.x * 256 + threadIdx.x;        // 0..16383
    float x = (float)j * (1.0f / 8192.0f);
    float sc = sqrtf(2.0f / 4096.0f);
    g_lut_c[j] = cospif(x) * sc;
    g_lut_s[j] = sinpif(x) * sc;
    float4 z4 = make_float4(0.f, 0.f, 0.f, 0.f);
#pragma unroll
    for (int t = 0; t < 4; t++)
        ((float4*)g_Acc)[j * 4 + t] = z4;
}

#define PI_F  3.14159274101257324f
#define PI_LO (-8.742277657347586e-8f)

__device__ __forceinline__ float dct_val(int n, int kk) {
    float t1 = 2.0f * (float)n + 1.0f;
    float t2 = PI_F * t1;
    float t3 = t2 * (float)kk;
    float th = t3 * (1.0f / 8192.0f);
    int m = (2 * n + 1) * kk;
    float x = (float)m * (1.0f / 8192.0f);
    float e = fmaf(-PI_F, x, th) - PI_LO * x;
    int j = m & 16383;
    return __ldg(&g_lut_c[j]) - e * __ldg(&g_lut_s[j]);
}

__global__ void k_build() {          // grid (128, 8), block (32, 8)
    __shared__ __half sh[32][33];
    const int tx = threadIdx.x, ty = threadIdx.y;
    const int n0 = blockIdx.x * 32, k0 = blockIdx.y * 32;
#pragma unroll
    for (int i = 0; i < 4; i++) {
        int kl = ty + i * 8;
        __half h = __float2half(dct_val(n0 + tx, k0 + kl + 1));
        int n = n0 + tx, kp = k0 + kl;           // B1: row = kp, kdim = n
        g_B1[(size_t)((kp >> 7) * 64 + (n >> 6)) * TB_EL + tile_off(kp & 127, n & 63)] = h;
        sh[kl][tx] = h;
    }
    __syncthreads();
#pragma unroll
    for (int i = 0; i < 4; i++) {
        int nl = ty + i * 8;
        int n = n0 + nl, kp = k0 + tx;           // B2: row = n, kdim = kp
        g_B2[(size_t)((n >> 7) * 4 + (kp >> 6)) * TB_EL + tile_off(n & 127, kp & 63)]
            = sh[tx][nl];
    }
}

__global__ void k_rho_h(const float* __restrict__ rho) {
    int i = blockIdx.x * 256 + threadIdx.x;      // float4 index
    int m = i >> 10, k = (i & 1023) * 4;
    float4 v = *(const float4*)(rho + (size_t)i * 4);
    __half2 p0 = __floats2half2_rn(v.x, v.y);
    __half2 p1 = __floats2half2_rn(v.z, v.w);
    uint2 u;
    u.x = *(const uint32_t*)&p0;
    u.y = *(const uint32_t*)&p1;
    size_t tb = (size_t)((m >> 7) * 64 + (k >> 6)) * TA_EL;
    *(uint2*)(g_A1 + tb + tile_off(m & 127, k & 63)) = u;
}

// -------- GEMM1: g_Acc += rho @ Cs^T (split-K=16, REDG epilogue) ------------
// CTA tile 128x128, 256 threads (8 warps, 4m x 2n), warp tile 32x64.
#define STAGE_B (16384 + 16384)
#define SMEM_SZ (1024 + 3 * STAGE_B)

__global__ void __launch_bounds__(256, 2) k_gemm1() {
    extern __shared__ char smem[];
    const uint32_t sb = smem_u32(smem);
    const int tid = threadIdx.x;
    const int lane = tid & 31;
    const int wid = tid >> 5;
    const int warp_m = wid & 3;
    const int warp_n = wid >> 2;                 // 0..1
    const int z = blockIdx.z;
    const __half* Abase = g_A1 + ((size_t)blockIdx.x * 64 + z * 4) * TA_EL;
    const __half* Bbase = g_B1 + ((size_t)blockIdx.y * 64 + z * 4) * TB_EL;

    if (tid == 0) {
        MBARRIER_INIT(sb + 0, 1);
        MBARRIER_INIT(sb + 8, 1);
        MBARRIER_INIT(sb + 16, 1);
    }
    __syncthreads();
    if (tid == 0) {
#pragma unroll
        for (int p = 0; p < 2; p++) {
            uint32_t dst = sb + 1024 + p * STAGE_B;
            MBARRIER_EXPECT_TX(sb + p * 8, STAGE_B);
            BULK_G2S(dst,         Abase + (size_t)p * TA_EL, 16384, sb + p * 8);
            BULK_G2S(dst + 16384, Bbase + (size_t)p * TB_EL, 16384, sb + p * 8);
        }
    }

    float acc[2][8][4];
#pragma unroll
    for (int mt = 0; mt < 2; mt++)
#pragma unroll
        for (int j = 0; j < 8; j++)
#pragma unroll
            for (int q = 0; q < 4; q++) acc[mt][j][q] = 0.f;

    const int a_row = (lane & 7) + ((lane >> 3) & 1) * 8;
    const int a_c   = lane >> 4;
    const int b_row = (lane & 7) + (lane >> 4) * 8;
    const int b_c   = (lane >> 3) & 1;

#pragma unroll
    for (int i = 0; i < 4; i++) {
        MBARRIER_WAIT_PARITY(sb + (i % 3) * 8, (i / 3) & 1);
        __syncthreads();
        if (tid == 0 && i + 2 < 4) {
            int s2 = (i + 2) % 3;
            uint32_t dst = sb + 1024 + s2 * STAGE_B;
            MBARRIER_EXPECT_TX(sb + s2 * 8, STAGE_B);
            BULK_G2S(dst,         Abase + (size_t)(i + 2) * TA_EL, 16384, sb + s2 * 8);
            BULK_G2S(dst + 16384, Bbase + (size_t)(i + 2) * TB_EL, 16384, sb + s2 * 8);
        }
        const uint32_t stA = sb + 1024 + (uint32_t)(i % 3) * STAGE_B;
        const uint32_t stB = stA + 16384u;
#pragma unroll
        for (int s = 0; s < 4; s++) {
            uint32_t ah[2][4];
#pragma unroll
            for (int mt = 0; mt < 2; mt++) {
                int r = warp_m * 32 + mt * 16 + a_row;
                int u = s * 2 + a_c;
                LDSM4(ah[mt], stA + (uint32_t)(r * 128 + ((u ^ (r & 7)) << 4)));
            }
#pragma unroll
            for (int nt = 0; nt < 4; nt++) {
                uint32_t bh[4];
                int r = warp_n * 64 + nt * 16 + b_row;
                int u = s * 2 + b_c;
                LDSM4(bh, stB + (uint32_t)(r * 128 + ((u ^ (r & 7)) << 4)));
#pragma unroll
                for (int mt = 0; mt < 2; mt++)
#pragma unroll
                    for (int h = 0; h < 2; h++)
                        MMA(acc[mt][nt * 2 + h], ah[mt], bh[h * 2], bh[h * 2 + 1]);
            }
        }
    }

    const int mbase = blockIdx.x * 128 + warp_m * 32;
    const int nbase = blockIdx.y * 128 + warp_n * 64;
#pragma unroll
    for (int mt = 0; mt < 2; mt++)
#pragma unroll
        for (int j = 0; j < 8; j++) {
            float* d = g_Acc + (size_t)(mbase + mt * 16 + (lane >> 2)) * RR
                             + nbase + j * 8 + (lane & 3) * 2;
            REDADD(d,            acc[mt][j][0]);
            REDADD(d + 1,        acc[mt][j][1]);
            REDADD(d + RR * 8,     acc[mt][j][2]);
            REDADD(d + RR * 8 + 1, acc[mt][j][3]);
        }
}

// -------- k_scale: Al = g_Acc * lam -> tiled fp16 ---------------------------
__global__ void k_scale(const float* __restrict__ lam) {
    int i = blockIdx.x * 256 + threadIdx.x;      // float4 over NB*RR/4
    int m = i >> 6, k = (i & 63) * 4;
    float4 s = *(const float4*)(g_Acc + (size_t)i * 4);
    s.x *= lam[k]; s.y *= lam[k + 1]; s.z *= lam[k + 2]; s.w *= lam[k + 3];
    __half2 q0 = __floats2half2_rn(s.x, s.y);
    __half2 q1 = __floats2half2_rn(s.z, s.w);
    uint2 u;
    u.x = *(const uint32_t*)&q0;
    u.y = *(const uint32_t*)&q1;
    size_t tb = (size_t)((m >> 7) * 4 + (k >> 6)) * TA_EL;
    *(uint2*)(g_A2 + tb + tile_off(m & 127, k & 63)) = u;
}

// -------- GEMM2: phi = Al @ Cs  (high-occupancy variant) --------------------
// CTA tile 128x128, 512 threads (16 warps, 4m x 4n), warp tile 32x32.
// 2 CTAs/SM -> 32 warps/SM. acc = 32 regs/thread (fits 64-reg cap).
__global__ void __launch_bounds__(512, 2) k_gemm2(float* __restrict__ out) {
    extern __shared__ char smem[];
    const uint32_t sb = smem_u32(smem);
    const int tid = threadIdx.x;
    const int lane = tid & 31;
    const int wid = tid >> 5;
    const int warp_m = wid & 3;
    const int warp_n = wid >> 2;                 // 0..3
    const __half* Abase = g_A2 + (size_t)blockIdx.x * 4 * TA_EL;
    const __half* Bbase = g_B2 + (size_t)blockIdx.y * 4 * TB_EL;

    if (tid == 0) {
        MBARRIER_INIT(sb + 0, 1);
        MBARRIER_INIT(sb + 8, 1);
        MBARRIER_INIT(sb + 16, 1);
    }
    __syncthreads();
    if (tid == 0) {
#pragma unroll
        for (int p = 0; p < 2; p++) {
            uint32_t dst = sb + 1024 + p * STAGE_B;
            MBARRIER_EXPECT_TX(sb + p * 8, STAGE_B);
            BULK_G2S(dst,         Abase + (size_t)p * TA_EL, 16384, sb + p * 8);
            BULK_G2S(dst + 16384, Bbase + (size_t)p * TB_EL, 16384, sb + p * 8);
        }
    }

    float acc[2][4][4];
#pragma unroll
    for (int mt = 0; mt < 2; mt++)
#pragma unroll
        for (int j = 0; j < 4; j++)
#pragma unroll
            for (int q = 0; q < 4; q++) acc[mt][j][q] = 0.f;

    const int a_row = (lane & 7) + ((lane >> 3) & 1) * 8;
    const int a_c   = lane >> 4;
    const int b_row = (lane & 7) + (lane >> 4) * 8;
    const int b_c   = (lane >> 3) & 1;

#pragma unroll
    for (int i = 0; i < 4; i++) {
        MBARRIER_WAIT_PARITY(sb + (i % 3) * 8, (i / 3) & 1);
        __syncthreads();
        if (tid == 0 && i + 2 < 4) {
            int s2 = (i + 2) % 3;
            uint32_t dst = sb + 1024 + s2 * STAGE_B;
            MBARRIER_EXPECT_TX(sb + s2 * 8, STAGE_B);
            BULK_G2S(dst,         Abase + (size_t)(i + 2) * TA_EL, 16384, sb + s2 * 8);
            BULK_G2S(dst + 16384, Bbase + (size_t)(i + 2) * TB_EL, 16384, sb + s2 * 8);
        }
        const uint32_t stA = sb + 1024 + (uint32_t)(i % 3) * STAGE_B;
        const uint32_t stB = stA + 16384u;
#pragma unroll
        for (int s = 0; s < 4; s++) {
            uint32_t ah[2][4];
#pragma unroll
            for (int mt = 0; mt < 2; mt++) {
                int r = warp_m * 32 + mt * 16 + a_row;
                int u = s * 2 + a_c;
                LDSM4(ah[mt], stA + (uint32_t)(r * 128 + ((u ^ (r & 7)) << 4)));
            }
#pragma unroll
            for (int nt = 0; nt < 2; nt++) {
                uint32_t bh[4];
                int r = warp_n * 32 + nt * 16 + b_row;
                int u = s * 2 + b_c;
                LDSM4(bh, stB + (uint32_t)(r * 128 + ((u ^ (r & 7)) << 4)));
#pragma unroll
                for (int mt = 0; mt < 2; mt++)
#pragma unroll
                    for (int h = 0; h < 2; h++)
                        MMA(acc[mt][nt * 2 + h], ah[mt], bh[h * 2], bh[h * 2 + 1]);
            }
        }
    }

    const int mbase = blockIdx.x * 128 + warp_m * 32;
    const int nbase = blockIdx.y * 128 + warp_n * 32;
#pragma unroll
    for (int mt = 0; mt < 2; mt++)
#pragma unroll
        for (int j = 0; j < 4; j++) {
            float* d = out + (size_t)(mbase + mt * 16 + (lane >> 2)) * NG
                           + nbase + j * 8 + (lane & 3) * 2;
            d[0] = acc[mt][j][0];
            d[1] = acc[mt][j][1];
            d[NG * 8]     = acc[mt][j][2];
            d[NG * 8 + 1] = acc[mt][j][3];
        }
}

extern "C" void kernel_launch(void* const* d_in, const int* in_sizes, int n_in,
                              void* d_out, int out_size) {
    const float* rho = (const float*)d_in[0];
    const float* lam = (const float*)d_in[1];
    float* phi = (float*)d_out;
    (void)in_sizes; (void)n_in; (void)out_size;

    cudaFuncSetAttribute(k_gemm1, cudaFuncAttributeMaxDynamicSharedMemorySize, SMEM_SZ);
    cudaFuncSetAttribute(k_gemm2, cudaFuncAttributeMaxDynamicSharedMemorySize, SMEM_SZ);

    k_lut<<<64, 256>>>();
    k_build<<<dim3(128, 8), dim3(32, 8)>>>();
    k_rho_h<<<(NB * NG) / 1024, 256>>>(rho);
    // GEMM1: g_Acc += rho @ Cs^T  (split-K=16 -> 256 CTAs, REDG epilogue)
    k_gemm1<<<dim3(8, 2, SPLITS), 256, SMEM_SZ>>>();
    k_scale<<<(NB * RR) / 1024, 256>>>(lam);
    // GEMM2: phi = Al @ Cs  (256 CTAs, 512 thr, 32 warps/SM)
    k_gemm2<<<dim3(8, 32), 512, SMEM_SZ>>>(phi);
}

// round 15
// speedup vs baseline: 1.0062x; 1.0062x over previous
#include <cuda_runtime.h>
#include <cuda_fp16.h>
#include <cstdint>

// phi = (lam ⊙ (rho @ Cs^T)) @ Cs, rank-256. B=1024, N=4096, R=256.
// R15: FULL-PREFETCH GEMM — each CTA's entire K-slice (192KB) is bulk-copied
// at kernel start via 8 concurrent cp.async.bulk (4 mbarriers, one/chunk).
// Copy latency paid once, zero steady-state waits, no ring, no loop syncs.
// CTA tile 128x256, 512 thr, 1 CTA/SM, single-wave 128-CTA grids.

#define NB 1024
#define NG 4096
#define RR 256
#define SPLITS 16
#define TA_EL 8192      // halfs per 128x64 A tile (16 KB)
#define TB_EL 16384     // halfs per 256x64 B tile (32 KB)

__device__ __align__(16) __half g_A1[NB * NG];     // rho tiled   [8 m][64 kc]
__device__ __align__(16) __half g_B1[RR * NG];     // Cs tiled    [1 n][64 kc]
__device__ __align__(16) __half g_B2[NG * RR];     // Cs^T tiled  [16 n][4 kc]
__device__ __align__(16) __half g_A2[NB * RR];     // Al tiled    [8 m][4 kc]
__device__ __align__(16) float g_Acc[NB * RR];     // 1 MB split-K accumulator
__device__ __align__(16) float g_lut_c[16384];
__device__ __align__(16) float g_lut_s[16384];

// ----------------------------- PTX helpers ---------------------------------
__device__ __forceinline__ uint32_t smem_u32(const void* p) {
    uint32_t a;
    asm("{ .reg .u64 t; cvta.to.shared.u64 t, %1; cvt.u32.u64 %0, t; }" : "=r"(a) : "l"(p));
    return a;
}
#define MBARRIER_INIT(addr, cnt) \
    asm volatile("mbarrier.init.shared.b64 [%0], %1;" :: "r"((uint32_t)(addr)), "r"((uint32_t)(cnt)) : "memory")
#define MBARRIER_EXPECT_TX(addr, bytes) \
    asm volatile("mbarrier.arrive.expect_tx.shared.b64 _, [%0], %1;" \
        :: "r"((uint32_t)(addr)), "r"((uint32_t)(bytes)) : "memory")
#define MBARRIER_WAIT_PARITY(addr, par) do { \
    uint32_t _mb = (uint32_t)(addr), _pa = (uint32_t)(par), _dn; \
    asm volatile("{\n\t.reg .pred p;\n\t" \
        "mbarrier.try_wait.parity.acquire.cta.shared::cta.b64 p, [%1], %2;\n\t" \
        "selp.b32 %0, 1, 0, p;\n\t}" : "=r"(_dn) : "r"(_mb), "r"(_pa) : "memory"); \
    if (!_dn) { \
        asm volatile("{\n\t.reg .pred P1;\n\tWL_%=:\n\t" \
            "mbarrier.try_wait.parity.acquire.cta.shared::cta.b64 P1, [%0], %1, 0x989680;\n\t" \
            "@P1 bra.uni WD_%=;\n\tbra.uni WL_%=;\n\tWD_%=:\n\t}" \
            :: "r"(_mb), "r"(_pa) : "memory"); \
    } } while (0)
#define BULK_G2S(dst, src, bytes, mbar) \
    asm volatile("cp.async.bulk.shared::cluster.global.mbarrier::complete_tx::bytes " \
                 "[%0], [%1], %2, [%3];" \
        :: "r"((uint32_t)(dst)), "l"(src), "r"((uint32_t)(bytes)), "r"((uint32_t)(mbar)) : "memory")
#define LDSM4(r, a) \
    asm volatile("ldmatrix.sync.aligned.m8n8.x4.shared.b16 {%0,%1,%2,%3}, [%4];" \
        : "=r"((r)[0]), "=r"((r)[1]), "=r"((r)[2]), "=r"((r)[3]) : "r"(a))
#define MMA(c, a, b0, b1) \
    asm volatile("mma.sync.aligned.m16n8k16.row.col.f32.f16.f16.f32 " \
        "{%0,%1,%2,%3},{%4,%5,%6,%7},{%8,%9},{%0,%1,%2,%3};" \
        : "+f"((c)[0]), "+f"((c)[1]), "+f"((c)[2]), "+f"((c)[3]) \
        : "r"((a)[0]), "r"((a)[1]), "r"((a)[2]), "r"((a)[3]), "r"(b0), "r"(b1))
#define REDADD(addr, v) \
    asm volatile("red.global.add.f32 [%0], %1;" :: "l"(addr), "f"(v) : "memory")

// Tile-internal offset (halfs): 64 halfs/row = 128 B; 16B unit u swizzled by row&7.
__device__ __forceinline__ int tile_off(int r, int kcol) {
    int u = kcol >> 3;
    return r * 64 + ((u ^ (r & 7)) << 3) + (kcol & 7);
}

// ------------------------------- LUT + builds -------------------------------
__global__ void k_lut() {            // also zeroes g_Acc (replayed per launch)
    int j = blockIdx.x * 256 + threadIdx.x;        // 0..16383
    float x = (float)j * (1.0f / 8192.0f);
    float sc = sqrtf(2.0f / 4096.0f);
    g_lut_c[j] = cospif(x) * sc;
    g_lut_s[j] = sinpif(x) * sc;
    float4 z4 = make_float4(0.f, 0.f, 0.f, 0.f);
#pragma unroll
    for (int t = 0; t < 4; t++)
        ((float4*)g_Acc)[j * 4 + t] = z4;
}

#define PI_F  3.14159274101257324f
#define PI_LO (-8.742277657347586e-8f)

__device__ __forceinline__ float dct_val(int n, int kk) {
    float t1 = 2.0f * (float)n + 1.0f;
    float t2 = PI_F * t1;
    float t3 = t2 * (float)kk;
    float th = t3 * (1.0f / 8192.0f);
    int m = (2 * n + 1) * kk;
    float x = (float)m * (1.0f / 8192.0f);
    float e = fmaf(-PI_F, x, th) - PI_LO * x;
    int j = m & 16383;
    return __ldg(&g_lut_c[j]) - e * __ldg(&g_lut_s[j]);
}

__global__ void k_build() {          // grid (128, 8), block (32, 8)
    __shared__ __half sh[32][33];
    const int tx = threadIdx.x, ty = threadIdx.y;
    const int n0 = blockIdx.x * 32, k0 = blockIdx.y * 32;
#pragma unroll
    for (int i = 0; i < 4; i++) {
        int kl = ty + i * 8;
        __half h = __float2half(dct_val(n0 + tx, k0 + kl + 1));
        int n = n0 + tx, kp = k0 + kl;   // B1: 256-row tile, row = kp, kdim = n
        g_B1[(size_t)(n >> 6) * TB_EL + tile_off(kp, n & 63)] = h;
        sh[kl][tx] = h;
    }
    __syncthreads();
#pragma unroll
    for (int i = 0; i < 4; i++) {
        int nl = ty + i * 8;
        int n = n0 + nl, kp = k0 + tx;   // B2: 256-row tiles, row = n, kdim = kp
        g_B2[(size_t)((n >> 8) * 4 + (kp >> 6)) * TB_EL + tile_off(n & 255, kp & 63)]
            = sh[tx][nl];
    }
}

__global__ void k_rho_h(const float* __restrict__ rho) {
    int i = blockIdx.x * 256 + threadIdx.x;      // float4 index
    int m = i >> 10, k = (i & 1023) * 4;
    float4 v = *(const float4*)(rho + (size_t)i * 4);
    __half2 p0 = __floats2half2_rn(v.x, v.y);
    __half2 p1 = __floats2half2_rn(v.z, v.w);
    uint2 u;
    u.x = *(const uint32_t*)&p0;
    u.y = *(const uint32_t*)&p1;
    size_t tb = (size_t)((m >> 7) * 64 + (k >> 6)) * TA_EL;
    *(uint2*)(g_A1 + tb + tile_off(m & 127, k & 63)) = u;
}

// ---------- full-prefetch HMMA GEMM: out[128x256 tile] = A @ B^T ------------
// 512 threads, 16 warps (4m x 4n), warp tile 32x64. NC=4 chunks of K=64,
// ALL chunk copies issued upfront (4 mbarriers), no ring, no loop syncs.
#define CHUNK_B 49152                     // 16K A + 32K B
#define SMEM_SZ (1024 + 4 * CHUNK_B)      // 197632

__global__ void __launch_bounds__(512, 1) k_gemm(
    const __half* __restrict__ A, const __half* __restrict__ B,
    float* __restrict__ out, int nkc_a, int nkc_b, int ldo, int use_red)
{
    extern __shared__ char smem[];
    const uint32_t sb = smem_u32(smem);
    const int tid = threadIdx.x;
    const int lane = tid & 31;
    const int wid = tid >> 5;
    const int warp_m = wid & 3;
    const int warp_n = wid >> 2;              // 0..3
    const int z = blockIdx.z;
    const __half* Abase = A + ((size_t)blockIdx.x * nkc_a + z * 4) * TA_EL;
    const __half* Bbase = B + ((size_t)blockIdx.y * nkc_b + z * 4) * TB_EL;

    if (tid == 0) {
#pragma unroll
        for (int i = 0; i < 4; i++) MBARRIER_INIT(sb + i * 8, 1);
    }
    __syncthreads();
    if (tid == 0) {
#pragma unroll
        for (int i = 0; i < 4; i++) {         // ALL copies in flight at once
            uint32_t dst = sb + 1024 + i * CHUNK_B;
            MBARRIER_EXPECT_TX(sb + i * 8, CHUNK_B);
            BULK_G2S(dst,         Abase + (size_t)i * TA_EL, 16384, sb + i * 8);
            BULK_G2S(dst + 16384, Bbase + (size_t)i * TB_EL, 32768, sb + i * 8);
        }
    }

    float acc[2][8][4];
#pragma unroll
    for (int mt = 0; mt < 2; mt++)
#pragma unroll
        for (int j = 0; j < 8; j++)
#pragma unroll
            for (int q = 0; q < 4; q++) acc[mt][j][q] = 0.f;

    const int a_row = (lane & 7) + ((lane >> 3) & 1) * 8;
    const int a_c   = lane >> 4;
    const int b_row = (lane & 7) + (lane >> 4) * 8;
    const int b_c   = (lane >> 3) & 1;

#pragma unroll
    for (int i = 0; i < 4; i++) {
        MBARRIER_WAIT_PARITY(sb + i * 8, 0);
        const uint32_t stA = sb + 1024 + (uint32_t)i * CHUNK_B;
        const uint32_t stB = stA + 16384u;
#pragma unroll
        for (int s = 0; s < 4; s++) {
            uint32_t ah[2][4];
#pragma unroll
            for (int mt = 0; mt < 2; mt++) {
                int r = warp_m * 32 + mt * 16 + a_row;
                int u = s * 2 + a_c;
                LDSM4(ah[mt], stA + (uint32_t)(r * 128 + ((u ^ (r & 7)) << 4)));
            }
#pragma unroll
            for (int nt = 0; nt < 4; nt++) {
                uint32_t bh[4];
                int r = warp_n * 64 + nt * 16 + b_row;
                int u = s * 2 + b_c;
                LDSM4(bh, stB + (uint32_t)(r * 128 + ((u ^ (r & 7)) << 4)));
#pragma unroll
                for (int mt = 0; mt < 2; mt++)
#pragma unroll
                    for (int h = 0; h < 2; h++)
                        MMA(acc[mt][nt * 2 + h], ah[mt], bh[h * 2], bh[h * 2 + 1]);
            }
        }
    }

    const int mbase = blockIdx.x * 128 + warp_m * 32;
    const int nbase = blockIdx.y * 256 + warp_n * 64;
    if (use_red) {
#pragma unroll
        for (int mt = 0; mt < 2; mt++)
#pragma unroll
            for (int j = 0; j < 8; j++) {
                float* d = out + (size_t)(mbase + mt * 16 + (lane >> 2)) * ldo
                               + nbase + j * 8 + (lane & 3) * 2;
                REDADD(d,           acc[mt][j][0]);
                REDADD(d + 1,       acc[mt][j][1]);
                REDADD(d + ldo * 8,     acc[mt][j][2]);
                REDADD(d + ldo * 8 + 1, acc[mt][j][3]);
            }
    } else {
#pragma unroll
        for (int mt = 0; mt < 2; mt++)
#pragma unroll
            for (int j = 0; j < 8; j++) {
                float* d = out + (size_t)(mbase + mt * 16 + (lane >> 2)) * ldo
                               + nbase + j * 8 + (lane & 3) * 2;
                d[0] = acc[mt][j][0];
                d[1] = acc[mt][j][1];
                d[ldo * 8]     = acc[mt][j][2];
                d[ldo * 8 + 1] = acc[mt][j][3];
            }
    }
}

// -------- k_scale: Al = g_Acc * lam -> tiled fp16 ---------------------------
__global__ void k_scale(const float* __restrict__ lam) {
    int i = blockIdx.x * 256 + threadIdx.x;      // float4 over NB*RR/4
    int m = i >> 6, k = (i & 63) * 4;
    float4 s = *(const float4*)(g_Acc + (size_t)i * 4);
    s.x *= lam[k]; s.y *= lam[k + 1]; s.z *= lam[k + 2]; s.w *= lam[k + 3];
    __half2 q0 = __floats2half2_rn(s.x, s.y);
    __half2 q1 = __floats2half2_rn(s.z, s.w);
    uint2 u;
    u.x = *(const uint32_t*)&q0;
    u.y = *(const uint32_t*)&q1;
    size_t tb = (size_t)((m >> 7) * 4 + (k >> 6)) * TA_EL;
    *(uint2*)(g_A2 + tb + tile_off(m & 127, k & 63)) = u;
}

extern "C" void kernel_launch(void* const* d_in, const int* in_sizes, int n_in,
                              void* d_out, int out_size) {
    const float* rho = (const float*)d_in[0];
    const float* lam = (const float*)d_in[1];
    float* phi = (float*)d_out;
    (void)in_sizes; (void)n_in; (void)out_size;

    __half *pA1, *pB1, *pB2, *pA2;
    float* pAcc;
    cudaGetSymbolAddress((void**)&pA1, g_A1);
    cudaGetSymbolAddress((void**)&pB1, g_B1);
    cudaGetSymbolAddress((void**)&pB2, g_B2);
    cudaGetSymbolAddress((void**)&pA2, g_A2);
    cudaGetSymbolAddress((void**)&pAcc, g_Acc);
    cudaFuncSetAttribute(k_gemm, cudaFuncAttributeMaxDynamicSharedMemorySize, SMEM_SZ);

    k_lut<<<64, 256>>>();
    k_build<<<dim3(128, 8), dim3(32, 8)>>>();
    k_rho_h<<<(NB * NG) / 1024, 256>>>(rho);
    // GEMM1: g_Acc += rho @ Cs^T   (grid (8,1,16) = 128 CTAs, REDG epilogue)
    k_gemm<<<dim3(8, 1, SPLITS), 512, SMEM_SZ>>>(pA1, pB1, pAcc, 64, 64, RR, 1);
    k_scale<<<(NB * RR) / 1024, 256>>>(lam);
    // GEMM2: phi = Al @ Cs         (grid (8,16) = 128 CTAs, direct store)
    k_gemm<<<dim3(8, 16, 1), 512, SMEM_SZ>>>(pA2, pB2, phi, 4, 4, NG, 0);
}